// round 5
// baseline (speedup 1.0000x reference)
#include <cuda_runtime.h>
#include <cuda_bf16.h>
#include <cstdint>
#include <math.h>

// ---------------------------------------------------------------------------
// Vocoder: conv-embed -> LN -> 8x ConvNeXt blocks -> LN -> head -> iSTFT
// GEMMs via mma.sync m16n8k16 bf16 with 2-way bf16 split, 3 passes
// (hi*hi + hi*lo + lo*hi): ~17-bit effective mantissa, fp32 accumulate.
// ---------------------------------------------------------------------------

#define B_      8
#define CM_     192
#define T_      2048
#define D_      512
#define H_      1536
#define BT_     (B_*T_)
#define NFFT_   1024
#define HOP_    256
#define NF_     513
#define TWO_NF_ 1026
#define KEMB_   (CM_*7)
#define LD_CAT  1040
#define L_FULL_ ((T_-1)*HOP_ + NFFT_)
#define L_OUT_  (L_FULL_ - NFFT_)

// ------------------------------- scratch -----------------------------------
__device__ float g_im2col[(size_t)BT_ * KEMB_];   // reused as S_cat (BT x LD_CAT)
__device__ float g_x [(size_t)BT_ * D_];
__device__ float g_y [(size_t)BT_ * D_];
__device__ float g_yn[(size_t)BT_ * D_];
__device__ float g_h [(size_t)BT_ * H_];          // pw1 out; reused as frames
__device__ float g_head[(size_t)BT_ * TWO_NF_];
__device__ float g_basis[(size_t)NFFT_ * LD_CAT];

// ------------------------------- helpers -----------------------------------
__device__ __forceinline__ uint32_t smem_to_u32(const void* p) {
    uint32_t a;
    asm("{ .reg .u64 t; cvta.to.shared.u64 t, %1; cvt.u32.u64 %0, t; }" : "=r"(a) : "l"(p));
    return a;
}
#define SWZ64(o) ((o) ^ (((o) >> 3) & 0x30))

__device__ __forceinline__ uint32_t b2u(__nv_bfloat162 h) {
    return *reinterpret_cast<uint32_t*>(&h);
}

__device__ __forceinline__ void mma16(float* c, const uint32_t* a, const uint32_t* b) {
    asm volatile("mma.sync.aligned.m16n8k16.row.col.f32.bf16.bf16.f32 "
        "{%0,%1,%2,%3}, {%4,%5,%6,%7}, {%8,%9}, {%0,%1,%2,%3};"
        : "+f"(c[0]), "+f"(c[1]), "+f"(c[2]), "+f"(c[3])
        : "r"(a[0]), "r"(a[1]), "r"(a[2]), "r"(a[3]), "r"(b[0]), "r"(b[1]));
}

#define LDSM4(r0, r1, r2, r3, addr) \
    asm volatile("ldmatrix.sync.aligned.m8n8.x4.shared.b16 {%0,%1,%2,%3}, [%4];" \
        : "=r"(r0), "=r"(r1), "=r"(r2), "=r"(r3) : "r"(addr))

// ------------------------------- GEMM --------------------------------------
// C[m,n] = epi( sum_k A[m,k]*B[n,k] ); A:(M,K) rm, B:(N,K) rm. Tile 128x128x32.
// SMEM per stage (bytes): A_hi[0,8K) A_lo[8K,16K) B_hi[16K,24K) B_lo[24K,32K)
// Each tile: 128 rows x 32 bf16 (64B rows), SW64 swizzled.
enum { EPI_BIAS = 0, EPI_GELU = 1, EPI_RES = 2, EPI_NONE = 3 };

#define STAGE_B 32768
#define SMEM_DYN (2 * STAGE_B)

// Load 16 fp32 from row, split each into bf16 hi/lo, pack k-pairs into u32.
__device__ __forceinline__ void gload_cvt(const float* __restrict__ src, int ld,
                                          int row, int nvalid, int K, int k0,
                                          uint32_t* uh, uint32_t* ul)
{
    const bool rv = row < nvalid;
    const float* p = src + (size_t)row * ld + k0;
    float v[16];
    if (rv && (k0 + 16 <= K)) {
#pragma unroll
        for (int q = 0; q < 4; q++) {
            float4 t = *(const float4*)(p + q * 4);
            v[q*4+0] = t.x; v[q*4+1] = t.y; v[q*4+2] = t.z; v[q*4+3] = t.w;
        }
    } else {
#pragma unroll
        for (int j = 0; j < 16; j++) v[j] = (rv && (k0 + j < K)) ? p[j] : 0.f;
    }
#pragma unroll
    for (int q = 0; q < 8; q++) {
        const float a = v[2*q], b = v[2*q+1];
        const float ha = __bfloat162float(__float2bfloat16_rn(a));
        const float hb = __bfloat162float(__float2bfloat16_rn(b));
        uh[q] = b2u(__floats2bfloat162_rn(ha, hb));
        ul[q] = b2u(__floats2bfloat162_rn(a - ha, b - hb));
    }
}

__device__ __forceinline__ void stage_put(char* stage,
                                          const uint32_t* uha, const uint32_t* ula,
                                          const uint32_t* uhb, const uint32_t* ulb,
                                          int tid)
{
    const int row = tid >> 1;
    const int b0 = row * 64 + (tid & 1) * 32;
    const uint32_t o0 = SWZ64((uint32_t)b0);
    const uint32_t o1 = SWZ64((uint32_t)(b0 + 16));
    *(uint4*)(stage + o0)          = make_uint4(uha[0], uha[1], uha[2], uha[3]);
    *(uint4*)(stage + o1)          = make_uint4(uha[4], uha[5], uha[6], uha[7]);
    *(uint4*)(stage + 8192 + o0)   = make_uint4(ula[0], ula[1], ula[2], ula[3]);
    *(uint4*)(stage + 8192 + o1)   = make_uint4(ula[4], ula[5], ula[6], ula[7]);
    *(uint4*)(stage + 16384 + o0)  = make_uint4(uhb[0], uhb[1], uhb[2], uhb[3]);
    *(uint4*)(stage + 16384 + o1)  = make_uint4(uhb[4], uhb[5], uhb[6], uhb[7]);
    *(uint4*)(stage + 24576 + o0)  = make_uint4(ulb[0], ulb[1], ulb[2], ulb[3]);
    *(uint4*)(stage + 24576 + o1)  = make_uint4(ulb[4], ulb[5], ulb[6], ulb[7]);
}

template<int EPI>
__global__ __launch_bounds__(256, 1)
void tcgemm(const float* __restrict__ A, const float* __restrict__ Bm,
            const float* __restrict__ bias, const float* __restrict__ gamma,
            float* __restrict__ C, int M, int N, int K,
            int lda, int ldb, int ldc)
{
    extern __shared__ char smem[];
    const uint32_t sbase = smem_to_u32(smem);
    const int tid  = threadIdx.x;
    const int wid  = tid >> 5;
    const int lane = tid & 31;
    const int wm   = wid & 1;          // M dim: 2 x 64
    const int wn   = wid >> 1;         // N dim: 4 x 32
    const int c_   = lane & 3;
    const int g_   = lane >> 2;
    const int row0 = blockIdx.y * 128;
    const int col0 = blockIdx.x * 128;

    float acc[4][4][4];
#pragma unroll
    for (int i = 0; i < 4; i++)
#pragma unroll
        for (int j = 0; j < 4; j++)
#pragma unroll
            for (int q = 0; q < 4; q++) acc[i][j][q] = 0.f;

    const float* Ap = A  + (size_t)row0 * lda;
    const float* Bp = Bm + (size_t)col0 * ldb;
    int nB = N - col0; if (nB > 128) nB = 128;
    const int nch = (K + 31) >> 5;
    const int myrow = tid >> 1;
    const int myk   = (tid & 1) * 16;

    uint32_t uha[8], ula[8], uhb[8], ulb[8];
    gload_cvt(Ap, lda, myrow, 128, K, myk, uha, ula);
    gload_cvt(Bp, ldb, myrow, nB,  K, myk, uhb, ulb);
    stage_put(smem, uha, ula, uhb, ulb, tid);
    __syncthreads();

    // ldmatrix per-lane offset pieces
    const int a_r8 = ((lane >> 3) & 1) * 8 + (lane & 7);  // A: m sub by bit3
    const int a_k16 = ((lane >> 4) & 1) * 16;              // A: k sub by bit4
    const int b_r8 = ((lane >> 4) & 1) * 8 + (lane & 7);   // B: n sub by bit4
    const int b_k16 = ((lane >> 3) & 1) * 16;              // B: k sub by bit3

    for (int ch = 0; ch < nch; ch++) {
        if (ch + 1 < nch) {
            const int k0n = (ch + 1) * 32 + myk;
            gload_cvt(Ap, lda, myrow, 128, K, k0n, uha, ula);
            gload_cvt(Bp, ldb, myrow, nB,  K, k0n, uhb, ulb);
        }
        const uint32_t st = sbase + (uint32_t)(ch & 1) * STAGE_B;

#pragma unroll
        for (int ks = 0; ks < 2; ks++) {
            uint32_t bh[4][2], bl[4][2];
#pragma unroll
            for (int np = 0; np < 2; np++) {
                const int nrow = wn * 32 + np * 16 + b_r8;
                const uint32_t off = SWZ64((uint32_t)(nrow * 64 + ks * 32 + b_k16));
                LDSM4(bh[np*2][0], bh[np*2][1], bh[np*2+1][0], bh[np*2+1][1],
                      st + 16384u + off);
                LDSM4(bl[np*2][0], bl[np*2][1], bl[np*2+1][0], bl[np*2+1][1],
                      st + 24576u + off);
            }
#pragma unroll
            for (int mf = 0; mf < 4; mf++) {
                const int arow = wm * 64 + mf * 16 + a_r8;
                const uint32_t offa = SWZ64((uint32_t)(arow * 64 + ks * 32 + a_k16));
                uint32_t ah[4], al[4];
                LDSM4(ah[0], ah[1], ah[2], ah[3], st + offa);
                LDSM4(al[0], al[1], al[2], al[3], st + 8192u + offa);
#pragma unroll
                for (int nf = 0; nf < 4; nf++) mma16(acc[mf][nf], ah, bh[nf]);
#pragma unroll
                for (int nf = 0; nf < 4; nf++) mma16(acc[mf][nf], ah, bl[nf]);
#pragma unroll
                for (int nf = 0; nf < 4; nf++) mma16(acc[mf][nf], al, bh[nf]);
            }
        }
        __syncthreads();
        if (ch + 1 < nch)
            stage_put(smem + ((ch + 1) & 1) * STAGE_B, uha, ula, uhb, ulb, tid);
        __syncthreads();
    }

    // epilogue straight from registers
#pragma unroll
    for (int mf = 0; mf < 4; mf++) {
        const int r = row0 + wm * 64 + mf * 16 + g_;
#pragma unroll
        for (int nf = 0; nf < 4; nf++) {
            const int col = col0 + wn * 32 + nf * 8 + c_ * 2;
            if (col < N) {
                float v0 = acc[mf][nf][0], v1 = acc[mf][nf][1];
                float v2 = acc[mf][nf][2], v3 = acc[mf][nf][3];
                if (EPI != EPI_NONE) {
                    const float2 bs = *(const float2*)&bias[col];
                    v0 += bs.x; v1 += bs.y; v2 += bs.x; v3 += bs.y;
                }
                if (EPI == EPI_GELU) {
                    v0 = 0.5f * v0 * (1.f + erff(v0 * 0.70710678118654752f));
                    v1 = 0.5f * v1 * (1.f + erff(v1 * 0.70710678118654752f));
                    v2 = 0.5f * v2 * (1.f + erff(v2 * 0.70710678118654752f));
                    v3 = 0.5f * v3 * (1.f + erff(v3 * 0.70710678118654752f));
                }
                float* p0 = C + (size_t)r * ldc + col;
                float* p1 = p0 + 8 * ldc;
                if (EPI == EPI_RES) {
                    const float2 gm = *(const float2*)&gamma[col];
                    float2 o0 = *(float2*)p0, o1 = *(float2*)p1;
                    o0.x += gm.x * v0; o0.y += gm.y * v1;
                    o1.x += gm.x * v2; o1.y += gm.y * v3;
                    *(float2*)p0 = o0; *(float2*)p1 = o1;
                } else {
                    *(float2*)p0 = make_float2(v0, v1);
                    *(float2*)p1 = make_float2(v2, v3);
                }
            }
        }
    }
}

// ------------------------------- LayerNorm ---------------------------------
__global__ __launch_bounds__(128)
void ln_kernel(const float* __restrict__ in, float* __restrict__ out,
               const float* __restrict__ w, const float* __restrict__ b)
{
    const int m = blockIdx.x;
    const int tid = threadIdx.x;
    const int lane = tid & 31, wid = tid >> 5;
    __shared__ float red[4];

    float4 v = ((const float4*)(in + (size_t)m * D_))[tid];
    float s = v.x + v.y + v.z + v.w;
#pragma unroll
    for (int o = 16; o; o >>= 1) s += __shfl_xor_sync(0xffffffffu, s, o);
    if (lane == 0) red[wid] = s;
    __syncthreads();
    const float mean = (red[0] + red[1] + red[2] + red[3]) * (1.f / 512.f);
    __syncthreads();

    const float dx = v.x - mean, dy = v.y - mean, dz = v.z - mean, dww = v.w - mean;
    float ss = dx * dx + dy * dy + dz * dz + dww * dww;
#pragma unroll
    for (int o = 16; o; o >>= 1) ss += __shfl_xor_sync(0xffffffffu, ss, o);
    if (lane == 0) red[wid] = ss;
    __syncthreads();
    const float var = (red[0] + red[1] + red[2] + red[3]) * (1.f / 512.f);
    const float inv = rsqrtf(var + 1e-5f);

    const float4 wv = ((const float4*)w)[tid];
    const float4 bv = ((const float4*)b)[tid];
    float4 o4;
    o4.x = dx  * inv * wv.x + bv.x;
    o4.y = dy  * inv * wv.y + bv.y;
    o4.z = dz  * inv * wv.z + bv.z;
    o4.w = dww * inv * wv.w + bv.w;
    ((float4*)(out + (size_t)m * D_))[tid] = o4;
}

// ------------------------------- im2col ------------------------------------
__global__ __launch_bounds__(256)
void im2col_kernel(const float* __restrict__ mel)
{
    const int idx = blockIdx.x * 256 + threadIdx.x;
    if (idx >= BT_ * KEMB_) return;
    const int m = idx / KEMB_;
    const int j = idx - m * KEMB_;
    const int c = j / 7, k = j - c * 7;
    const int bb = m >> 11, tt = m & (T_ - 1);
    const int t2 = tt + k - 3;
    g_im2col[idx] = ((unsigned)t2 < (unsigned)T_)
                  ? mel[((size_t)bb * CM_ + c) * T_ + t2] : 0.f;
}

// ------------------------------- depthwise conv ----------------------------
__global__ __launch_bounds__(256)
void dwconv_kernel(const float* __restrict__ x, float* __restrict__ y,
                   const float* __restrict__ wgt, const float* __restrict__ bias)
{
    const int idx = blockIdx.x * 256 + threadIdx.x;
    if (idx >= BT_ * (D_ / 4)) return;
    const int dv = idx & 127;
    const int m  = idx >> 7;
    const int d  = dv * 4;
    const int bb = m >> 11, tt = m & (T_ - 1);

    float4 acc;
    acc.x = bias[d]; acc.y = bias[d + 1]; acc.z = bias[d + 2]; acc.w = bias[d + 3];
#pragma unroll
    for (int k = 0; k < 7; k++) {
        const int t2 = tt + k - 3;
        if ((unsigned)t2 < (unsigned)T_) {
            const float4 xv = *(const float4*)(x + ((size_t)(bb * T_ + t2) * D_ + d));
            acc.x = fmaf(xv.x, wgt[(d + 0) * 7 + k], acc.x);
            acc.y = fmaf(xv.y, wgt[(d + 1) * 7 + k], acc.y);
            acc.z = fmaf(xv.z, wgt[(d + 2) * 7 + k], acc.z);
            acc.w = fmaf(xv.w, wgt[(d + 3) * 7 + k], acc.w);
        }
    }
    *(float4*)(y + (size_t)m * D_ + d) = acc;
}

// ------------------------------- S_cat -------------------------------------
__global__ __launch_bounds__(256)
void scat_kernel()
{
    const int idx = blockIdx.x * 256 + threadIdx.x;
    if (idx >= BT_ * NF_) return;
    const int m = idx / NF_;
    const int f = idx - m * NF_;
    const float* ho = g_head + (size_t)m * TWO_NF_;
    const float mag = fminf(expf(ho[f]), 100.f);
    const float ph  = ho[NF_ + f];
    float sp, cp;
    sincosf(ph, &sp, &cp);
    float* sc = g_im2col + (size_t)m * LD_CAT;
    sc[f]       = mag * cp;
    sc[NF_ + f] = mag * sp;
}

// ------------------------------- iSTFT basis -------------------------------
__global__ __launch_bounds__(256)
void basis_kernel(const float* __restrict__ window)
{
    const int idx = blockIdx.x * 256 + threadIdx.x;
    if (idx >= NFFT_ * NF_) return;
    const int n = idx / NF_;
    const int f = idx - n * NF_;
    const float scale = (f == 0 || f == NF_ - 1) ? (1.f / 1024.f) : (2.f / 1024.f);
    const float a1  = 6.28318530717958647692f * (float)n;
    const float ang = (a1 * (float)f) * (1.f / 1024.f);
    float s, c;
    sincosf(ang, &s, &c);
    const float wn = window[n] * scale;
    g_basis[(size_t)n * LD_CAT + f]       =  c * wn;
    g_basis[(size_t)n * LD_CAT + NF_ + f] = -s * wn;
}

// ------------------------------- overlap-add -------------------------------
__global__ __launch_bounds__(256)
void ola_kernel(const float* __restrict__ window, float* __restrict__ out)
{
    const int idx = blockIdx.x * 256 + threadIdx.x;
    if (idx >= B_ * L_OUT_) return;
    const int b  = idx / L_OUT_;
    const int lo = idx - b * L_OUT_;
    const int l  = lo + NFFT_ / 2;

    int thi = l >> 8;              if (thi > T_ - 1) thi = T_ - 1;
    int tlo = (l - (NFFT_ - 1) + (HOP_ - 1)) >> 8;  if (tlo < 0) tlo = 0;

    float a = 0.f, e = 0.f;
    for (int t = tlo; t <= thi; t++) {
        const int n = l - (t << 8);
        a += g_h[((size_t)(b * T_ + t) << 10) + n];
        const float wv = window[n];
        e += wv * wv;
    }
    out[idx] = a / (e + 1e-11f);
}

// ------------------------------- launch ------------------------------------
extern "C" void kernel_launch(void* const* d_in, const int* in_sizes, int n_in,
                              void* d_out, int out_size)
{
    const float* mel     = (const float*)d_in[0];
    const float* embed_w = (const float*)d_in[1];
    const float* embed_b = (const float*)d_in[2];
    const float* norm_w  = (const float*)d_in[3];
    const float* norm_b  = (const float*)d_in[4];
    const float* dw_w    = (const float*)d_in[5];
    const float* dw_b    = (const float*)d_in[6];
    const float* bn_w    = (const float*)d_in[7];
    const float* bn_b    = (const float*)d_in[8];
    const float* pw1_w   = (const float*)d_in[9];
    const float* pw1_b   = (const float*)d_in[10];
    const float* pw2_w   = (const float*)d_in[11];
    const float* pw2_b   = (const float*)d_in[12];
    const float* gamma   = (const float*)d_in[13];
    const float* fnorm_w = (const float*)d_in[14];
    const float* fnorm_b = (const float*)d_in[15];
    const float* head_w  = (const float*)d_in[16];
    const float* head_b  = (const float*)d_in[17];
    const float* window  = (const float*)d_in[18];
    float* out = (float*)d_out;

    float *p_im2col, *p_x, *p_y, *p_yn, *p_h, *p_head, *p_basis;
    cudaGetSymbolAddress((void**)&p_im2col, g_im2col);
    cudaGetSymbolAddress((void**)&p_x,      g_x);
    cudaGetSymbolAddress((void**)&p_y,      g_y);
    cudaGetSymbolAddress((void**)&p_yn,     g_yn);
    cudaGetSymbolAddress((void**)&p_h,      g_h);
    cudaGetSymbolAddress((void**)&p_head,   g_head);
    cudaGetSymbolAddress((void**)&p_basis,  g_basis);

    cudaFuncSetAttribute(tcgemm<EPI_BIAS>, cudaFuncAttributeMaxDynamicSharedMemorySize, SMEM_DYN);
    cudaFuncSetAttribute(tcgemm<EPI_GELU>, cudaFuncAttributeMaxDynamicSharedMemorySize, SMEM_DYN);
    cudaFuncSetAttribute(tcgemm<EPI_RES >, cudaFuncAttributeMaxDynamicSharedMemorySize, SMEM_DYN);
    cudaFuncSetAttribute(tcgemm<EPI_NONE>, cudaFuncAttributeMaxDynamicSharedMemorySize, SMEM_DYN);

    const dim3 blk(256);
    const int MT = BT_ / 128;

    // 1) embed conv: im2col + GEMM (N=512, K=1344), LN -> x
    im2col_kernel<<<(BT_ * KEMB_ + 255) / 256, blk>>>(mel);
    tcgemm<EPI_BIAS><<<dim3(D_ / 128, MT), blk, SMEM_DYN>>>(
        p_im2col, embed_w, embed_b, nullptr, p_y, BT_, D_, KEMB_, KEMB_, KEMB_, D_);
    ln_kernel<<<BT_, 128>>>(p_y, p_x, norm_w, norm_b);

    // 2) 8 ConvNeXt blocks
    for (int i = 0; i < 8; i++) {
        dwconv_kernel<<<(BT_ * (D_ / 4) + 255) / 256, blk>>>(
            p_x, p_y, dw_w + (size_t)i * D_ * 7, dw_b + (size_t)i * D_);
        ln_kernel<<<BT_, 128>>>(p_y, p_yn, bn_w + (size_t)i * D_, bn_b + (size_t)i * D_);
        tcgemm<EPI_GELU><<<dim3(H_ / 128, MT), blk, SMEM_DYN>>>(
            p_yn, pw1_w + (size_t)i * H_ * D_, pw1_b + (size_t)i * H_, nullptr,
            p_h, BT_, H_, D_, D_, D_, H_);
        tcgemm<EPI_RES><<<dim3(D_ / 128, MT), blk, SMEM_DYN>>>(
            p_h, pw2_w + (size_t)i * D_ * H_, pw2_b + (size_t)i * D_,
            gamma + (size_t)i * D_, p_x, BT_, D_, H_, H_, H_, D_);
    }

    // 3) final LN + head (N=1026, K=512)
    ln_kernel<<<BT_, 128>>>(p_x, p_yn, fnorm_w, fnorm_b);
    tcgemm<EPI_BIAS><<<dim3((TWO_NF_ + 127) / 128, MT), blk, SMEM_DYN>>>(
        p_yn, head_w, head_b, nullptr, p_head, BT_, TWO_NF_, D_, D_, D_, TWO_NF_);

    // 4) iSTFT: S_cat, basis, frames GEMM (N=1024, K=1026), overlap-add
    scat_kernel<<<(BT_ * NF_ + 255) / 256, blk>>>();
    basis_kernel<<<(NFFT_ * NF_ + 255) / 256, blk>>>(window);
    tcgemm<EPI_NONE><<<dim3(NFFT_ / 128, MT), blk, SMEM_DYN>>>(
        p_im2col, p_basis, nullptr, nullptr, p_h, BT_, NFFT_, TWO_NF_, LD_CAT, LD_CAT, NFFT_);
    ola_kernel<<<(B_ * L_OUT_ + 255) / 256, blk>>>(window, out);
}

// round 8
// speedup vs baseline: 1.3853x; 1.3853x over previous
#include <cuda_runtime.h>
#include <cuda_bf16.h>
#include <cstdint>
#include <math.h>

// ---------------------------------------------------------------------------
// Vocoder: conv-embed -> LN -> 8x ConvNeXt blocks -> LN -> head -> iSTFT
// GEMMs: mma.sync m16n8k16 bf16, 2-way bf16 split (hi+lo), 3 passes.
// All operands pre-split into bf16 hi/lo arrays by producers; GEMM mainloop
// is pure cp.async + ldmatrix + HMMA (no conversion on the critical path).
// ---------------------------------------------------------------------------

#define B_      8
#define CM_     192
#define T_      2048
#define D_      512
#define H_      1536
#define BT_     (B_*T_)
#define NFFT_   1024
#define HOP_    256
#define NF_     513
#define TWO_NF_ 1026
#define KEMB_   (CM_*7)        // 1344
#define KPAD_   1056           // frames GEMM K (1026 padded to mult of 32)
#define NHEADP_ 1152           // head weight rows padded to mult of 128
#define L_FULL_ ((T_-1)*HOP_ + NFFT_)
#define L_OUT_  (L_FULL_ - NFFT_)

typedef __nv_bfloat16 bf16;

// ------------------------------- scratch -----------------------------------
// bf16 hi/lo operand arrays (16B aligned for cp.async)
__device__ __align__(16) bf16 g_i2c_h[(size_t)BT_ * KEMB_];  // also S_cat (ld KPAD_)
__device__ __align__(16) bf16 g_i2c_l[(size_t)BT_ * KEMB_];
__device__ __align__(16) bf16 g_yn_h [(size_t)BT_ * D_];
__device__ __align__(16) bf16 g_yn_l [(size_t)BT_ * D_];
__device__ __align__(16) bf16 g_hh   [(size_t)BT_ * H_];
__device__ __align__(16) bf16 g_hl   [(size_t)BT_ * H_];
__device__ __align__(16) bf16 g_bas_h[(size_t)NFFT_ * KPAD_];
__device__ __align__(16) bf16 g_bas_l[(size_t)NFFT_ * KPAD_];

// weights: [embed | pw1 | pw2 | head(padded)]
#define OFF_WE  0
#define N_WE    (D_ * KEMB_)                    // 688128
#define OFF_P1  (OFF_WE + N_WE)
#define N_P1    (8 * H_ * D_)                   // 6291456
#define OFF_P2  (OFF_P1 + N_P1)
#define N_P2    (8 * D_ * H_)                   // 6291456
#define OFF_HD  (OFF_P2 + N_P2)
#define N_HD    (NHEADP_ * D_)                  // 589824
#define N_WTOT  (OFF_HD + N_HD)
__device__ __align__(16) bf16 g_wh[N_WTOT];
__device__ __align__(16) bf16 g_wl[N_WTOT];

// fp32 buffers
__device__ float g_x [(size_t)BT_ * D_];
__device__ float g_y [(size_t)BT_ * D_];
__device__ float g_head[(size_t)BT_ * TWO_NF_];
__device__ float g_frames[(size_t)BT_ * NFFT_];

// ------------------------------- helpers -----------------------------------
__device__ __forceinline__ uint32_t smem_to_u32(const void* p) {
    uint32_t a;
    asm("{ .reg .u64 t; cvta.to.shared.u64 t, %1; cvt.u32.u64 %0, t; }" : "=r"(a) : "l"(p));
    return a;
}
#define SWZ64(o) ((o) ^ (((o) >> 3) & 0x30))

__device__ __forceinline__ void split2(float v, bf16& h, bf16& l) {
    h = __float2bfloat16_rn(v);
    l = __float2bfloat16_rn(v - __bfloat162float(h));
}

__device__ __forceinline__ void mma16(float* c, const uint32_t* a, const uint32_t* b) {
    asm volatile("mma.sync.aligned.m16n8k16.row.col.f32.bf16.bf16.f32 "
        "{%0,%1,%2,%3}, {%4,%5,%6,%7}, {%8,%9}, {%0,%1,%2,%3};"
        : "+f"(c[0]), "+f"(c[1]), "+f"(c[2]), "+f"(c[3])
        : "r"(a[0]), "r"(a[1]), "r"(a[2]), "r"(a[3]), "r"(b[0]), "r"(b[1]));
}

#define LDSM4(r0, r1, r2, r3, addr) \
    asm volatile("ldmatrix.sync.aligned.m8n8.x4.shared.b16 {%0,%1,%2,%3}, [%4];" \
        : "=r"(r0), "=r"(r1), "=r"(r2), "=r"(r3) : "r"(addr))

#define CP16(dst, src) \
    asm volatile("cp.async.cg.shared.global [%0], [%1], 16;" \
                 :: "r"(dst), "l"(src) : "memory")
#define CP_COMMIT() asm volatile("cp.async.commit_group;" ::: "memory")
#define CP_WAIT2()  asm volatile("cp.async.wait_group 2;"  ::: "memory")

// ------------------------------- GEMM --------------------------------------
// C[m,n] = epi( sum_k A[m,k]*B[n,k] ); A,B pre-split bf16 hi/lo, row-major.
// Tile 128x128x32, 8 warps (2x4), NST=4 cp.async stages.
// Stage (32KB): Ah[0,8K) Al[8K,16K) Bh[16K,24K) Bl[24K,32K); 64B rows, SW64.
enum { EPI_BIAS = 0, EPI_GELU = 1, EPI_RES = 2, EPI_NONE = 3 };

#define NST     4
#define STAGE_B 32768
#define SMEM_DYN (NST * STAGE_B)

__device__ __forceinline__ void load_stage(uint32_t st,
    const bf16* __restrict__ Ah, const bf16* __restrict__ Al,
    const bf16* __restrict__ Bh, const bf16* __restrict__ Bl,
    int lda, int ldb, int k0, int tid)
{
    const int r  = tid >> 1;
    const int qb = (tid & 1) * 32;                  // byte offset within 64B row
    // NOTE: swizzle each 16B chunk address independently — SWZ64(x)+16 !=
    // SWZ64(x+16) when mask bit4 is set (caused the R7 OOB cp.async).
    const uint32_t o0 = SWZ64((uint32_t)(r * 64 + qb));
    const uint32_t o1 = SWZ64((uint32_t)(r * 64 + qb + 16));
    const char* pah = (const char*)(Ah + (size_t)r * lda + k0) + qb;
    const char* pal = (const char*)(Al + (size_t)r * lda + k0) + qb;
    const char* pbh = (const char*)(Bh + (size_t)r * ldb + k0) + qb;
    const char* pbl = (const char*)(Bl + (size_t)r * ldb + k0) + qb;
    CP16(st + o0,          pah); CP16(st + o1,          pah + 16);
    CP16(st + 8192  + o0,  pal); CP16(st + 8192  + o1,  pal + 16);
    CP16(st + 16384 + o0,  pbh); CP16(st + 16384 + o1,  pbh + 16);
    CP16(st + 24576 + o0,  pbl); CP16(st + 24576 + o1,  pbl + 16);
    CP_COMMIT();
}

template<int EPI>
__global__ __launch_bounds__(256)
void bgemm(const bf16* __restrict__ Ah, const bf16* __restrict__ Al,
           const bf16* __restrict__ Bh, const bf16* __restrict__ Bl,
           const float* __restrict__ bias, const float* __restrict__ gamma,
           float* __restrict__ C, bf16* __restrict__ Oh, bf16* __restrict__ Ol,
           int N, int K, int lda, int ldb, int ldc)
{
    extern __shared__ char smem[];
    const uint32_t sbase = smem_to_u32(smem);
    const int tid  = threadIdx.x;
    const int wid  = tid >> 5;
    const int lane = tid & 31;
    const int wm   = wid & 1;          // M: 2 x 64
    const int wn   = wid >> 1;         // N: 4 x 32
    const int c_   = lane & 3;
    const int g_   = lane >> 2;
    const int row0 = blockIdx.y * 128;
    const int col0 = blockIdx.x * 128;

    Ah += (size_t)row0 * lda;  Al += (size_t)row0 * lda;
    Bh += (size_t)col0 * ldb;  Bl += (size_t)col0 * ldb;

    float acc[4][4][4];
#pragma unroll
    for (int i = 0; i < 4; i++)
#pragma unroll
        for (int j = 0; j < 4; j++)
#pragma unroll
            for (int q = 0; q < 4; q++) acc[i][j][q] = 0.f;

    const int nch = K >> 5;            // K is always a multiple of 32

    // prologue: fill NST-1 stages
#pragma unroll
    for (int s = 0; s < NST - 1; s++)
        load_stage(sbase + s * STAGE_B, Ah, Al, Bh, Bl, lda, ldb, s * 32, tid);

    // ldmatrix per-lane offset pieces (fragment layout for m16n8k16)
    const int a_r8  = ((lane >> 3) & 1) * 8 + (lane & 7);
    const int a_k16 = ((lane >> 4) & 1) * 16;
    const int b_r8  = ((lane >> 4) & 1) * 8 + (lane & 7);
    const int b_k16 = ((lane >> 3) & 1) * 16;

    for (int ch = 0; ch < nch; ch++) {
        CP_WAIT2();
        __syncthreads();
        if (ch + NST - 1 < nch) {
            load_stage(sbase + ((ch + NST - 1) % NST) * STAGE_B,
                       Ah, Al, Bh, Bl, lda, ldb, (ch + NST - 1) * 32, tid);
        } else {
            CP_COMMIT();   // keep commit-index == chunk-index so WAIT2 drains tail
        }

        const uint32_t st = sbase + (uint32_t)(ch % NST) * STAGE_B;
#pragma unroll
        for (int ks = 0; ks < 2; ks++) {
            uint32_t bh[4][2], bl[4][2];
#pragma unroll
            for (int np = 0; np < 2; np++) {
                const int nrow = wn * 32 + np * 16 + b_r8;
                const uint32_t off = SWZ64((uint32_t)(nrow * 64 + ks * 32 + b_k16));
                LDSM4(bh[np*2][0], bh[np*2][1], bh[np*2+1][0], bh[np*2+1][1],
                      st + 16384u + off);
                LDSM4(bl[np*2][0], bl[np*2][1], bl[np*2+1][0], bl[np*2+1][1],
                      st + 24576u + off);
            }
#pragma unroll
            for (int mf = 0; mf < 4; mf++) {
                const int arow = wm * 64 + mf * 16 + a_r8;
                const uint32_t offa = SWZ64((uint32_t)(arow * 64 + ks * 32 + a_k16));
                uint32_t ah[4], al[4];
                LDSM4(ah[0], ah[1], ah[2], ah[3], st + offa);
                LDSM4(al[0], al[1], al[2], al[3], st + 8192u + offa);
#pragma unroll
                for (int nf = 0; nf < 4; nf++) mma16(acc[mf][nf], ah, bh[nf]);
#pragma unroll
                for (int nf = 0; nf < 4; nf++) mma16(acc[mf][nf], ah, bl[nf]);
#pragma unroll
                for (int nf = 0; nf < 4; nf++) mma16(acc[mf][nf], al, bh[nf]);
            }
        }
    }

    // ---------------- register epilogue ----------------
#pragma unroll
    for (int mf = 0; mf < 4; mf++) {
        const int r = row0 + wm * 64 + mf * 16 + g_;
#pragma unroll
        for (int nf = 0; nf < 4; nf++) {
            const int col = col0 + wn * 32 + nf * 8 + c_ * 2;
            if (col < N) {
                float v0 = acc[mf][nf][0], v1 = acc[mf][nf][1];
                float v2 = acc[mf][nf][2], v3 = acc[mf][nf][3];
                if (EPI != EPI_NONE) {
                    const float2 bs = *(const float2*)&bias[col];
                    v0 += bs.x; v1 += bs.y; v2 += bs.x; v3 += bs.y;
                }
                if (EPI == EPI_GELU) {
                    v0 = 0.5f * v0 * (1.f + erff(v0 * 0.70710678118654752f));
                    v1 = 0.5f * v1 * (1.f + erff(v1 * 0.70710678118654752f));
                    v2 = 0.5f * v2 * (1.f + erff(v2 * 0.70710678118654752f));
                    v3 = 0.5f * v3 * (1.f + erff(v3 * 0.70710678118654752f));
                    // write split bf16 hi/lo
                    bf16 h0, l0, h1, l1, h2, l2, h3, l3;
                    split2(v0, h0, l0); split2(v1, h1, l1);
                    split2(v2, h2, l2); split2(v3, h3, l3);
                    __nv_bfloat162* ph0 = (__nv_bfloat162*)(Oh + (size_t)r * ldc + col);
                    __nv_bfloat162* pl0 = (__nv_bfloat162*)(Ol + (size_t)r * ldc + col);
                    __nv_bfloat162* ph1 = (__nv_bfloat162*)(Oh + (size_t)(r + 8) * ldc + col);
                    __nv_bfloat162* pl1 = (__nv_bfloat162*)(Ol + (size_t)(r + 8) * ldc + col);
                    *ph0 = __nv_bfloat162(h0, h1);  *pl0 = __nv_bfloat162(l0, l1);
                    *ph1 = __nv_bfloat162(h2, h3);  *pl1 = __nv_bfloat162(l2, l3);
                } else {
                    float* p0 = C + (size_t)r * ldc + col;
                    float* p1 = p0 + 8 * ldc;
                    if (EPI == EPI_RES) {
                        const float2 gm = *(const float2*)&gamma[col];
                        float2 o0 = *(float2*)p0, o1 = *(float2*)p1;
                        o0.x += gm.x * v0; o0.y += gm.y * v1;
                        o1.x += gm.x * v2; o1.y += gm.y * v3;
                        *(float2*)p0 = o0; *(float2*)p1 = o1;
                    } else {
                        *(float2*)p0 = make_float2(v0, v1);
                        *(float2*)p1 = make_float2(v2, v3);
                    }
                }
            }
        }
    }
}

// ------------------------------- LayerNorm ---------------------------------
template<bool SPLIT>
__global__ __launch_bounds__(128)
void ln_kernel(const float* __restrict__ in, float* __restrict__ outf,
               bf16* __restrict__ outh, bf16* __restrict__ outl,
               const float* __restrict__ w, const float* __restrict__ b)
{
    const int m = blockIdx.x;
    const int tid = threadIdx.x;
    const int lane = tid & 31, wid = tid >> 5;
    __shared__ float red[4];

    float4 v = ((const float4*)(in + (size_t)m * D_))[tid];
    float s = v.x + v.y + v.z + v.w;
#pragma unroll
    for (int o = 16; o; o >>= 1) s += __shfl_xor_sync(0xffffffffu, s, o);
    if (lane == 0) red[wid] = s;
    __syncthreads();
    const float mean = (red[0] + red[1] + red[2] + red[3]) * (1.f / 512.f);
    __syncthreads();

    const float dx = v.x - mean, dy = v.y - mean, dz = v.z - mean, dww = v.w - mean;
    float ss = dx * dx + dy * dy + dz * dz + dww * dww;
#pragma unroll
    for (int o = 16; o; o >>= 1) ss += __shfl_xor_sync(0xffffffffu, ss, o);
    if (lane == 0) red[wid] = ss;
    __syncthreads();
    const float var = (red[0] + red[1] + red[2] + red[3]) * (1.f / 512.f);
    const float inv = rsqrtf(var + 1e-5f);

    const float4 wv = ((const float4*)w)[tid];
    const float4 bv = ((const float4*)b)[tid];
    float o0 = dx  * inv * wv.x + bv.x;
    float o1 = dy  * inv * wv.y + bv.y;
    float o2 = dz  * inv * wv.z + bv.z;
    float o3 = dww * inv * wv.w + bv.w;
    if (SPLIT) {
        bf16 h0,l0,h1,l1,h2,l2,h3,l3;
        split2(o0,h0,l0); split2(o1,h1,l1); split2(o2,h2,l2); split2(o3,h3,l3);
        __nv_bfloat162* ph = (__nv_bfloat162*)(outh + (size_t)m * D_ + tid * 4);
        __nv_bfloat162* pl = (__nv_bfloat162*)(outl + (size_t)m * D_ + tid * 4);
        ph[0] = __nv_bfloat162(h0, h1); ph[1] = __nv_bfloat162(h2, h3);
        pl[0] = __nv_bfloat162(l0, l1); pl[1] = __nv_bfloat162(l2, l3);
    } else {
        ((float4*)(outf + (size_t)m * D_))[tid] = make_float4(o0, o1, o2, o3);
    }
}

// ------------------------------- weight split ------------------------------
__global__ __launch_bounds__(256)
void cvt_split_kernel(const float* __restrict__ in, bf16* __restrict__ hi,
                      bf16* __restrict__ lo, int n_valid, int n_total)
{
    const int idx = blockIdx.x * 256 + threadIdx.x;
    if (idx >= n_total) return;
    const float v = (idx < n_valid) ? in[idx] : 0.f;
    bf16 h, l; split2(v, h, l);
    hi[idx] = h; lo[idx] = l;
}

// ------------------------------- im2col (split) ----------------------------
__global__ __launch_bounds__(256)
void im2col_kernel(const float* __restrict__ mel)
{
    const int idx = blockIdx.x * 256 + threadIdx.x;
    if (idx >= BT_ * KEMB_) return;
    const int m = idx / KEMB_;
    const int j = idx - m * KEMB_;
    const int c = j / 7, k = j - c * 7;
    const int bb = m >> 11, tt = m & (T_ - 1);
    const int t2 = tt + k - 3;
    const float v = ((unsigned)t2 < (unsigned)T_)
                  ? mel[((size_t)bb * CM_ + c) * T_ + t2] : 0.f;
    bf16 h, l; split2(v, h, l);
    g_i2c_h[idx] = h; g_i2c_l[idx] = l;
}

// ------------------------------- depthwise conv ----------------------------
__global__ __launch_bounds__(256)
void dwconv_kernel(const float* __restrict__ x, float* __restrict__ y,
                   const float* __restrict__ wgt, const float* __restrict__ bias)
{
    const int idx = blockIdx.x * 256 + threadIdx.x;
    if (idx >= BT_ * (D_ / 4)) return;
    const int dv = idx & 127;
    const int m  = idx >> 7;
    const int d  = dv * 4;
    const int bb = m >> 11, tt = m & (T_ - 1);

    float4 acc;
    acc.x = bias[d]; acc.y = bias[d + 1]; acc.z = bias[d + 2]; acc.w = bias[d + 3];
#pragma unroll
    for (int k = 0; k < 7; k++) {
        const int t2 = tt + k - 3;
        if ((unsigned)t2 < (unsigned)T_) {
            const float4 xv = *(const float4*)(x + ((size_t)(bb * T_ + t2) * D_ + d));
            acc.x = fmaf(xv.x, wgt[(d + 0) * 7 + k], acc.x);
            acc.y = fmaf(xv.y, wgt[(d + 1) * 7 + k], acc.y);
            acc.z = fmaf(xv.z, wgt[(d + 2) * 7 + k], acc.z);
            acc.w = fmaf(xv.w, wgt[(d + 3) * 7 + k], acc.w);
        }
    }
    *(float4*)(y + (size_t)m * D_ + d) = acc;
}

// ------------------------------- S_cat (split, ld KPAD_) -------------------
__global__ __launch_bounds__(256)
void scat_kernel()
{
    const int idx = blockIdx.x * 256 + threadIdx.x;
    if (idx >= BT_ * NF_) return;
    const int m = idx / NF_;
    const int f = idx - m * NF_;
    const float* ho = g_head + (size_t)m * TWO_NF_;
    const float mag = fminf(expf(ho[f]), 100.f);
    const float ph  = ho[NF_ + f];
    float sp, cp;
    sincosf(ph, &sp, &cp);
    bf16* sh = g_i2c_h + (size_t)m * KPAD_;
    bf16* sl = g_i2c_l + (size_t)m * KPAD_;
    bf16 h, l;
    split2(mag * cp, h, l);  sh[f] = h;        sl[f] = l;
    split2(mag * sp, h, l);  sh[NF_ + f] = h;  sl[NF_ + f] = l;
    if (f < KPAD_ - TWO_NF_) {                 // zero the K padding (30 cols)
        sh[TWO_NF_ + f] = __float2bfloat16_rn(0.f);
        sl[TWO_NF_ + f] = __float2bfloat16_rn(0.f);
    }
}

// ------------------------------- iSTFT basis (split, ld KPAD_) -------------
__global__ __launch_bounds__(256)
void basis_kernel(const float* __restrict__ window)
{
    const int idx = blockIdx.x * 256 + threadIdx.x;
    if (idx >= NFFT_ * NF_) return;
    const int n = idx / NF_;
    const int f = idx - n * NF_;
    const float scale = (f == 0 || f == NF_ - 1) ? (1.f / 1024.f) : (2.f / 1024.f);
    const float a1  = 6.28318530717958647692f * (float)n;
    const float ang = (a1 * (float)f) * (1.f / 1024.f);
    float s, c;
    sincosf(ang, &s, &c);
    const float wn = window[n] * scale;
    bf16* bh = g_bas_h + (size_t)n * KPAD_;
    bf16* bl = g_bas_l + (size_t)n * KPAD_;
    bf16 h, l;
    split2( c * wn, h, l);  bh[f] = h;        bl[f] = l;
    split2(-s * wn, h, l);  bh[NF_ + f] = h;  bl[NF_ + f] = l;
    if (f < KPAD_ - TWO_NF_) {
        bh[TWO_NF_ + f] = __float2bfloat16_rn(0.f);
        bl[TWO_NF_ + f] = __float2bfloat16_rn(0.f);
    }
}

// ------------------------------- overlap-add -------------------------------
__global__ __launch_bounds__(256)
void ola_kernel(const float* __restrict__ window, float* __restrict__ out)
{
    const int idx = blockIdx.x * 256 + threadIdx.x;
    if (idx >= B_ * L_OUT_) return;
    const int b  = idx / L_OUT_;
    const int lo = idx - b * L_OUT_;
    const int l  = lo + NFFT_ / 2;

    int thi = l >> 8;              if (thi > T_ - 1) thi = T_ - 1;
    int tlo = (l - (NFFT_ - 1) + (HOP_ - 1)) >> 8;  if (tlo < 0) tlo = 0;

    float a = 0.f, e = 0.f;
    for (int t = tlo; t <= thi; t++) {
        const int n = l - (t << 8);
        a += g_frames[((size_t)(b * T_ + t) << 10) + n];
        const float wv = window[n];
        e += wv * wv;
    }
    out[idx] = a / (e + 1e-11f);
}

// ------------------------------- launch ------------------------------------
extern "C" void kernel_launch(void* const* d_in, const int* in_sizes, int n_in,
                              void* d_out, int out_size)
{
    const float* mel     = (const float*)d_in[0];
    const float* embed_w = (const float*)d_in[1];
    const float* embed_b = (const float*)d_in[2];
    const float* norm_w  = (const float*)d_in[3];
    const float* norm_b  = (const float*)d_in[4];
    const float* dw_w    = (const float*)d_in[5];
    const float* dw_b    = (const float*)d_in[6];
    const float* bn_w    = (const float*)d_in[7];
    const float* bn_b    = (const float*)d_in[8];
    const float* pw1_w   = (const float*)d_in[9];
    const float* pw1_b   = (const float*)d_in[10];
    const float* pw2_w   = (const float*)d_in[11];
    const float* pw2_b   = (const float*)d_in[12];
    const float* gamma   = (const float*)d_in[13];
    const float* fnorm_w = (const float*)d_in[14];
    const float* fnorm_b = (const float*)d_in[15];
    const float* head_w  = (const float*)d_in[16];
    const float* head_b  = (const float*)d_in[17];
    const float* window  = (const float*)d_in[18];
    float* out = (float*)d_out;

    float *p_x, *p_y, *p_head, *p_frames;
    bf16 *p_i2c_h, *p_i2c_l, *p_yn_h, *p_yn_l, *p_hh, *p_hl, *p_bh, *p_bl, *p_wh, *p_wl;
    cudaGetSymbolAddress((void**)&p_x,      g_x);
    cudaGetSymbolAddress((void**)&p_y,      g_y);
    cudaGetSymbolAddress((void**)&p_head,   g_head);
    cudaGetSymbolAddress((void**)&p_frames, g_frames);
    cudaGetSymbolAddress((void**)&p_i2c_h,  g_i2c_h);
    cudaGetSymbolAddress((void**)&p_i2c_l,  g_i2c_l);
    cudaGetSymbolAddress((void**)&p_yn_h,   g_yn_h);
    cudaGetSymbolAddress((void**)&p_yn_l,   g_yn_l);
    cudaGetSymbolAddress((void**)&p_hh,     g_hh);
    cudaGetSymbolAddress((void**)&p_hl,     g_hl);
    cudaGetSymbolAddress((void**)&p_bh,     g_bas_h);
    cudaGetSymbolAddress((void**)&p_bl,     g_bas_l);
    cudaGetSymbolAddress((void**)&p_wh,     g_wh);
    cudaGetSymbolAddress((void**)&p_wl,     g_wl);

    cudaFuncSetAttribute(bgemm<EPI_BIAS>, cudaFuncAttributeMaxDynamicSharedMemorySize, SMEM_DYN);
    cudaFuncSetAttribute(bgemm<EPI_GELU>, cudaFuncAttributeMaxDynamicSharedMemorySize, SMEM_DYN);
    cudaFuncSetAttribute(bgemm<EPI_RES >, cudaFuncAttributeMaxDynamicSharedMemorySize, SMEM_DYN);
    cudaFuncSetAttribute(bgemm<EPI_NONE>, cudaFuncAttributeMaxDynamicSharedMemorySize, SMEM_DYN);

    const dim3 blk(256);
    const int MT = BT_ / 128;

    // 0) split weights into bf16 hi/lo (head padded with zero rows)
    cvt_split_kernel<<<(N_WE + 255) / 256, blk>>>(embed_w, p_wh + OFF_WE, p_wl + OFF_WE, N_WE, N_WE);
    cvt_split_kernel<<<(N_P1 + 255) / 256, blk>>>(pw1_w,   p_wh + OFF_P1, p_wl + OFF_P1, N_P1, N_P1);
    cvt_split_kernel<<<(N_P2 + 255) / 256, blk>>>(pw2_w,   p_wh + OFF_P2, p_wl + OFF_P2, N_P2, N_P2);
    cvt_split_kernel<<<(N_HD + 255) / 256, blk>>>(head_w,  p_wh + OFF_HD, p_wl + OFF_HD,
                                                  TWO_NF_ * D_, N_HD);

    // 1) embed conv: im2col(split) + GEMM (N=512, K=1344), LN -> x (fp32)
    im2col_kernel<<<(BT_ * KEMB_ + 255) / 256, blk>>>(mel);
    bgemm<EPI_BIAS><<<dim3(D_ / 128, MT), blk, SMEM_DYN>>>(
        p_i2c_h, p_i2c_l, p_wh + OFF_WE, p_wl + OFF_WE,
        embed_b, nullptr, p_y, nullptr, nullptr, D_, KEMB_, KEMB_, KEMB_, D_);
    ln_kernel<false><<<BT_, 128>>>(p_y, p_x, nullptr, nullptr, norm_w, norm_b);

    // 2) 8 ConvNeXt blocks
    for (int i = 0; i < 8; i++) {
        dwconv_kernel<<<(BT_ * (D_ / 4) + 255) / 256, blk>>>(
            p_x, p_y, dw_w + (size_t)i * D_ * 7, dw_b + (size_t)i * D_);
        ln_kernel<true><<<BT_, 128>>>(p_y, nullptr, p_yn_h, p_yn_l,
                                      bn_w + (size_t)i * D_, bn_b + (size_t)i * D_);
        bgemm<EPI_GELU><<<dim3(H_ / 128, MT), blk, SMEM_DYN>>>(
            p_yn_h, p_yn_l, p_wh + OFF_P1 + (size_t)i * H_ * D_, p_wl + OFF_P1 + (size_t)i * H_ * D_,
            pw1_b + (size_t)i * H_, nullptr, nullptr, p_hh, p_hl, H_, D_, D_, D_, H_);
        bgemm<EPI_RES><<<dim3(D_ / 128, MT), blk, SMEM_DYN>>>(
            p_hh, p_hl, p_wh + OFF_P2 + (size_t)i * D_ * H_, p_wl + OFF_P2 + (size_t)i * D_ * H_,
            pw2_b + (size_t)i * D_, gamma + (size_t)i * D_, p_x, nullptr, nullptr,
            D_, H_, H_, H_, D_);
    }

    // 3) final LN (split) + head (N=1026, K=512, B rows padded to 1152)
    ln_kernel<true><<<BT_, 128>>>(p_x, nullptr, p_yn_h, p_yn_l, fnorm_w, fnorm_b);
    bgemm<EPI_BIAS><<<dim3(NHEADP_ / 128, MT), blk, SMEM_DYN>>>(
        p_yn_h, p_yn_l, p_wh + OFF_HD, p_wl + OFF_HD,
        head_b, nullptr, p_head, nullptr, nullptr, TWO_NF_, D_, D_, D_, TWO_NF_);

    // 4) iSTFT: S_cat(split, K padded), basis(split), frames GEMM, overlap-add
    scat_kernel<<<(BT_ * NF_ + 255) / 256, blk>>>();
    basis_kernel<<<(NFFT_ * NF_ + 255) / 256, blk>>>(window);
    bgemm<EPI_NONE><<<dim3(NFFT_ / 128, MT), blk, SMEM_DYN>>>(
        p_i2c_h, p_i2c_l, p_bh, p_bl, nullptr, nullptr, p_frames, nullptr, nullptr,
        NFFT_, KPAD_, KPAD_, KPAD_, NFFT_);
    ola_kernel<<<(B_ * L_OUT_ + 255) / 256, blk>>>(window, out);
}

// round 11
// speedup vs baseline: 1.5718x; 1.1346x over previous
#include <cuda_runtime.h>
#include <cuda_bf16.h>
#include <cstdint>
#include <math.h>

// ---------------------------------------------------------------------------
// Vocoder: conv-embed -> LN -> 8x ConvNeXt blocks -> LN -> head -> iSTFT
// GEMMs: mma.sync m16n8k16 bf16, 2-way bf16 split (hi+lo), 3 passes.
// Mainloop: pure cp.async + ldmatrix + HMMA; NST=3 stages, 2 CTAs/SM.
// ---------------------------------------------------------------------------

#define B_      8
#define CM_     192
#define T_      2048
#define D_      512
#define H_      1536
#define BT_     (B_*T_)
#define NFFT_   1024
#define HOP_    256
#define NF_     513
#define TWO_NF_ 1026
#define KEMB_   (CM_*7)        // 1344
#define KPAD_   1056           // frames GEMM K (1026 padded to mult of 32)
#define NHEADP_ 1152           // head weight rows padded to mult of 128
#define L_FULL_ ((T_-1)*HOP_ + NFFT_)
#define L_OUT_  (L_FULL_ - NFFT_)

typedef __nv_bfloat16 bf16;

// ------------------------------- scratch -----------------------------------
__device__ __align__(16) bf16 g_i2c_h[(size_t)BT_ * KEMB_];  // also S_cat (ld KPAD_)
__device__ __align__(16) bf16 g_i2c_l[(size_t)BT_ * KEMB_];
__device__ __align__(16) bf16 g_yn_h [(size_t)BT_ * D_];
__device__ __align__(16) bf16 g_yn_l [(size_t)BT_ * D_];
__device__ __align__(16) bf16 g_hh   [(size_t)BT_ * H_];
__device__ __align__(16) bf16 g_hl   [(size_t)BT_ * H_];
__device__ __align__(16) bf16 g_bas_h[(size_t)NFFT_ * KPAD_];
__device__ __align__(16) bf16 g_bas_l[(size_t)NFFT_ * KPAD_];

// weights: [embed | pw1 | pw2 | head(padded)]
#define OFF_WE  0
#define N_WE    (D_ * KEMB_)
#define OFF_P1  (OFF_WE + N_WE)
#define N_P1    (8 * H_ * D_)
#define OFF_P2  (OFF_P1 + N_P1)
#define N_P2    (8 * D_ * H_)
#define OFF_HD  (OFF_P2 + N_P2)
#define N_HD    (NHEADP_ * D_)
#define N_WTOT  (OFF_HD + N_HD)
__device__ __align__(16) bf16 g_wh[N_WTOT];
__device__ __align__(16) bf16 g_wl[N_WTOT];

// fp32 buffers
__device__ float g_x [(size_t)BT_ * D_];
__device__ float g_y [(size_t)BT_ * D_];
__device__ float g_head[(size_t)BT_ * TWO_NF_];
__device__ float g_frames[(size_t)BT_ * NFFT_];

// ------------------------------- helpers -----------------------------------
__device__ __forceinline__ uint32_t smem_to_u32(const void* p) {
    uint32_t a;
    asm("{ .reg .u64 t; cvta.to.shared.u64 t, %1; cvt.u32.u64 %0, t; }" : "=r"(a) : "l"(p));
    return a;
}
#define SWZ64(o) ((o) ^ (((o) >> 3) & 0x30))

__device__ __forceinline__ void split2(float v, bf16& h, bf16& l) {
    h = __float2bfloat16_rn(v);
    l = __float2bfloat16_rn(v - __bfloat162float(h));
}

__device__ __forceinline__ void mma16(float* c, const uint32_t* a, const uint32_t* b) {
    asm volatile("mma.sync.aligned.m16n8k16.row.col.f32.bf16.bf16.f32 "
        "{%0,%1,%2,%3}, {%4,%5,%6,%7}, {%8,%9}, {%0,%1,%2,%3};"
        : "+f"(c[0]), "+f"(c[1]), "+f"(c[2]), "+f"(c[3])
        : "r"(a[0]), "r"(a[1]), "r"(a[2]), "r"(a[3]), "r"(b[0]), "r"(b[1]));
}

#define LDSM4(r0, r1, r2, r3, addr) \
    asm volatile("ldmatrix.sync.aligned.m8n8.x4.shared.b16 {%0,%1,%2,%3}, [%4];" \
        : "=r"(r0), "=r"(r1), "=r"(r2), "=r"(r3) : "r"(addr))

#define CP16(dst, src) \
    asm volatile("cp.async.cg.shared.global [%0], [%1], 16;" \
                 :: "r"(dst), "l"(src) : "memory")
#define CP_COMMIT() asm volatile("cp.async.commit_group;" ::: "memory")
#define CP_WAIT1()  asm volatile("cp.async.wait_group 1;"  ::: "memory")

// ------------------------------- GEMM --------------------------------------
// C[m,n] = epi( sum_k A[m,k]*B[n,k] ); A,B pre-split bf16 hi/lo, row-major.
// Tile 128x128x32, 8 warps (2x4), NST=3 cp.async stages, 2 CTAs/SM.
// Stage (32KB): Ah[0,8K) Al[8K,16K) Bh[16K,24K) Bl[24K,32K); 64B rows, SW64.
enum { EPI_BIAS = 0, EPI_GELU = 1, EPI_RES = 2, EPI_NONE = 3 };

#define NST     3
#define STAGE_B 32768
#define SMEM_DYN (NST * STAGE_B)

__device__ __forceinline__ void load_stage(uint32_t st,
    const bf16* __restrict__ Ah, const bf16* __restrict__ Al,
    const bf16* __restrict__ Bh, const bf16* __restrict__ Bl,
    int lda, int ldb, int k0, int tid)
{
    const int r  = tid >> 1;
    const int qb = (tid & 1) * 32;
    // swizzle each 16B chunk independently (SWZ64(x)+16 != SWZ64(x+16))
    const uint32_t o0 = SWZ64((uint32_t)(r * 64 + qb));
    const uint32_t o1 = SWZ64((uint32_t)(r * 64 + qb + 16));
    const char* pah = (const char*)(Ah + (size_t)r * lda + k0) + qb;
    const char* pal = (const char*)(Al + (size_t)r * lda + k0) + qb;
    const char* pbh = (const char*)(Bh + (size_t)r * ldb + k0) + qb;
    const char* pbl = (const char*)(Bl + (size_t)r * ldb + k0) + qb;
    CP16(st + o0,          pah); CP16(st + o1,          pah + 16);
    CP16(st + 8192  + o0,  pal); CP16(st + 8192  + o1,  pal + 16);
    CP16(st + 16384 + o0,  pbh); CP16(st + 16384 + o1,  pbh + 16);
    CP16(st + 24576 + o0,  pbl); CP16(st + 24576 + o1,  pbl + 16);
    CP_COMMIT();
}

template<int EPI>
__global__ __launch_bounds__(256, 2)
void bgemm(const bf16* __restrict__ Ah, const bf16* __restrict__ Al,
           const bf16* __restrict__ Bh, const bf16* __restrict__ Bl,
           const float* __restrict__ bias, const float* __restrict__ gamma,
           float* __restrict__ C, bf16* __restrict__ Oh, bf16* __restrict__ Ol,
           int N, int K, int lda, int ldb, int ldc)
{
    extern __shared__ char smem[];
    const uint32_t sbase = smem_to_u32(smem);
    const int tid  = threadIdx.x;
    const int wid  = tid >> 5;
    const int lane = tid & 31;
    const int wm   = wid & 1;          // M: 2 x 64
    const int wn   = wid >> 1;         // N: 4 x 32
    const int c_   = lane & 3;
    const int g_   = lane >> 2;
    const int row0 = blockIdx.y * 128;
    const int col0 = blockIdx.x * 128;

    Ah += (size_t)row0 * lda;  Al += (size_t)row0 * lda;
    Bh += (size_t)col0 * ldb;  Bl += (size_t)col0 * ldb;

    float acc[4][4][4];
#pragma unroll
    for (int i = 0; i < 4; i++)
#pragma unroll
        for (int j = 0; j < 4; j++)
#pragma unroll
            for (int q = 0; q < 4; q++) acc[i][j][q] = 0.f;

    const int nch = K >> 5;

    // prologue: fill NST-1 stages
#pragma unroll
    for (int s = 0; s < NST - 1; s++)
        load_stage(sbase + s * STAGE_B, Ah, Al, Bh, Bl, lda, ldb, s * 32, tid);

    const int a_r8  = ((lane >> 3) & 1) * 8 + (lane & 7);
    const int a_k16 = ((lane >> 4) & 1) * 16;
    const int b_r8  = ((lane >> 4) & 1) * 8 + (lane & 7);
    const int b_k16 = ((lane >> 3) & 1) * 16;

    for (int ch = 0; ch < nch; ch++) {
        CP_WAIT1();
        __syncthreads();
        if (ch + NST - 1 < nch) {
            load_stage(sbase + ((ch + NST - 1) % NST) * STAGE_B,
                       Ah, Al, Bh, Bl, lda, ldb, (ch + NST - 1) * 32, tid);
        } else {
            CP_COMMIT();   // keep commit-index == chunk-index so WAIT1 drains tail
        }

        const uint32_t st = sbase + (uint32_t)(ch % NST) * STAGE_B;
#pragma unroll
        for (int ks = 0; ks < 2; ks++) {
            uint32_t bh[4][2], bl[4][2];
#pragma unroll
            for (int np = 0; np < 2; np++) {
                const int nrow = wn * 32 + np * 16 + b_r8;
                const uint32_t off = SWZ64((uint32_t)(nrow * 64 + ks * 32 + b_k16));
                LDSM4(bh[np*2][0], bh[np*2][1], bh[np*2+1][0], bh[np*2+1][1],
                      st + 16384u + off);
                LDSM4(bl[np*2][0], bl[np*2][1], bl[np*2+1][0], bl[np*2+1][1],
                      st + 24576u + off);
            }
#pragma unroll
            for (int mf = 0; mf < 4; mf++) {
                const int arow = wm * 64 + mf * 16 + a_r8;
                const uint32_t offa = SWZ64((uint32_t)(arow * 64 + ks * 32 + a_k16));
                uint32_t ah[4], al[4];
                LDSM4(ah[0], ah[1], ah[2], ah[3], st + offa);
                LDSM4(al[0], al[1], al[2], al[3], st + 8192u + offa);
#pragma unroll
                for (int nf = 0; nf < 4; nf++) mma16(acc[mf][nf], ah, bh[nf]);
#pragma unroll
                for (int nf = 0; nf < 4; nf++) mma16(acc[mf][nf], ah, bl[nf]);
#pragma unroll
                for (int nf = 0; nf < 4; nf++) mma16(acc[mf][nf], al, bh[nf]);
            }
        }
    }

    // ---------------- register epilogue ----------------
#pragma unroll
    for (int mf = 0; mf < 4; mf++) {
        const int r = row0 + wm * 64 + mf * 16 + g_;
#pragma unroll
        for (int nf = 0; nf < 4; nf++) {
            const int col = col0 + wn * 32 + nf * 8 + c_ * 2;
            if (col < N) {
                float v0 = acc[mf][nf][0], v1 = acc[mf][nf][1];
                float v2 = acc[mf][nf][2], v3 = acc[mf][nf][3];
                if (EPI != EPI_NONE) {
                    const float2 bs = *(const float2*)&bias[col];
                    v0 += bs.x; v1 += bs.y; v2 += bs.x; v3 += bs.y;
                }
                if (EPI == EPI_GELU) {
                    v0 = 0.5f * v0 * (1.f + erff(v0 * 0.70710678118654752f));
                    v1 = 0.5f * v1 * (1.f + erff(v1 * 0.70710678118654752f));
                    v2 = 0.5f * v2 * (1.f + erff(v2 * 0.70710678118654752f));
                    v3 = 0.5f * v3 * (1.f + erff(v3 * 0.70710678118654752f));
                    bf16 h0, l0, h1, l1, h2, l2, h3, l3;
                    split2(v0, h0, l0); split2(v1, h1, l1);
                    split2(v2, h2, l2); split2(v3, h3, l3);
                    __nv_bfloat162* ph0 = (__nv_bfloat162*)(Oh + (size_t)r * ldc + col);
                    __nv_bfloat162* pl0 = (__nv_bfloat162*)(Ol + (size_t)r * ldc + col);
                    __nv_bfloat162* ph1 = (__nv_bfloat162*)(Oh + (size_t)(r + 8) * ldc + col);
                    __nv_bfloat162* pl1 = (__nv_bfloat162*)(Ol + (size_t)(r + 8) * ldc + col);
                    *ph0 = __nv_bfloat162(h0, h1);  *pl0 = __nv_bfloat162(l0, l1);
                    *ph1 = __nv_bfloat162(h2, h3);  *pl1 = __nv_bfloat162(l2, l3);
                } else {
                    float* p0 = C + (size_t)r * ldc + col;
                    float* p1 = p0 + 8 * ldc;
                    if (EPI == EPI_RES) {
                        const float2 gm = *(const float2*)&gamma[col];
                        float2 o0 = *(float2*)p0, o1 = *(float2*)p1;
                        o0.x += gm.x * v0; o0.y += gm.y * v1;
                        o1.x += gm.x * v2; o1.y += gm.y * v3;
                        *(float2*)p0 = o0; *(float2*)p1 = o1;
                    } else {
                        *(float2*)p0 = make_float2(v0, v1);
                        *(float2*)p1 = make_float2(v2, v3);
                    }
                }
            }
        }
    }
}

// ------------------- fused depthwise conv + LayerNorm + split --------------
// One block per token: 128 threads, 4 channels each. dwconv(7 taps) -> LN ->
// bf16 hi/lo split store. Removes the g_y round-trip entirely.
__global__ __launch_bounds__(128)
void dwln_kernel(const float* __restrict__ x,
                 const float* __restrict__ wgt, const float* __restrict__ dbias,
                 const float* __restrict__ nw, const float* __restrict__ nb,
                 bf16* __restrict__ outh, bf16* __restrict__ outl)
{
    const int m = blockIdx.x;
    const int tid = threadIdx.x;
    const int lane = tid & 31, wid = tid >> 5;
    const int d = tid * 4;
    const int bb = m >> 11, tt = m & (T_ - 1);
    __shared__ float red[4];

    float4 acc;
    acc.x = dbias[d]; acc.y = dbias[d + 1]; acc.z = dbias[d + 2]; acc.w = dbias[d + 3];
#pragma unroll
    for (int k = 0; k < 7; k++) {
        const int t2 = tt + k - 3;
        if ((unsigned)t2 < (unsigned)T_) {
            const float4 xv = *(const float4*)(x + ((size_t)(bb * T_ + t2) * D_ + d));
            acc.x = fmaf(xv.x, wgt[(d + 0) * 7 + k], acc.x);
            acc.y = fmaf(xv.y, wgt[(d + 1) * 7 + k], acc.y);
            acc.z = fmaf(xv.z, wgt[(d + 2) * 7 + k], acc.z);
            acc.w = fmaf(xv.w, wgt[(d + 3) * 7 + k], acc.w);
        }
    }

    float s = acc.x + acc.y + acc.z + acc.w;
#pragma unroll
    for (int o = 16; o; o >>= 1) s += __shfl_xor_sync(0xffffffffu, s, o);
    if (lane == 0) red[wid] = s;
    __syncthreads();
    const float mean = (red[0] + red[1] + red[2] + red[3]) * (1.f / 512.f);
    __syncthreads();

    const float dx = acc.x - mean, dy = acc.y - mean, dz = acc.z - mean, dw = acc.w - mean;
    float ss = dx * dx + dy * dy + dz * dz + dw * dw;
#pragma unroll
    for (int o = 16; o; o >>= 1) ss += __shfl_xor_sync(0xffffffffu, ss, o);
    if (lane == 0) red[wid] = ss;
    __syncthreads();
    const float var = (red[0] + red[1] + red[2] + red[3]) * (1.f / 512.f);
    const float inv = rsqrtf(var + 1e-5f);

    const float4 wv = ((const float4*)nw)[tid];
    const float4 bv = ((const float4*)nb)[tid];
    const float o0 = dx * inv * wv.x + bv.x;
    const float o1 = dy * inv * wv.y + bv.y;
    const float o2 = dz * inv * wv.z + bv.z;
    const float o3 = dw * inv * wv.w + bv.w;

    bf16 h0,l0,h1,l1,h2,l2,h3,l3;
    split2(o0,h0,l0); split2(o1,h1,l1); split2(o2,h2,l2); split2(o3,h3,l3);
    __nv_bfloat162* ph = (__nv_bfloat162*)(outh + (size_t)m * D_ + d);
    __nv_bfloat162* pl = (__nv_bfloat162*)(outl + (size_t)m * D_ + d);
    ph[0] = __nv_bfloat162(h0, h1); ph[1] = __nv_bfloat162(h2, h3);
    pl[0] = __nv_bfloat162(l0, l1); pl[1] = __nv_bfloat162(l2, l3);
}

// ------------------------------- LayerNorm ---------------------------------
template<bool SPLIT>
__global__ __launch_bounds__(128)
void ln_kernel(const float* __restrict__ in, float* __restrict__ outf,
               bf16* __restrict__ outh, bf16* __restrict__ outl,
               const float* __restrict__ w, const float* __restrict__ b)
{
    const int m = blockIdx.x;
    const int tid = threadIdx.x;
    const int lane = tid & 31, wid = tid >> 5;
    __shared__ float red[4];

    float4 v = ((const float4*)(in + (size_t)m * D_))[tid];
    float s = v.x + v.y + v.z + v.w;
#pragma unroll
    for (int o = 16; o; o >>= 1) s += __shfl_xor_sync(0xffffffffu, s, o);
    if (lane == 0) red[wid] = s;
    __syncthreads();
    const float mean = (red[0] + red[1] + red[2] + red[3]) * (1.f / 512.f);
    __syncthreads();

    const float dx = v.x - mean, dy = v.y - mean, dz = v.z - mean, dww = v.w - mean;
    float ss = dx * dx + dy * dy + dz * dz + dww * dww;
#pragma unroll
    for (int o = 16; o; o >>= 1) ss += __shfl_xor_sync(0xffffffffu, ss, o);
    if (lane == 0) red[wid] = ss;
    __syncthreads();
    const float var = (red[0] + red[1] + red[2] + red[3]) * (1.f / 512.f);
    const float inv = rsqrtf(var + 1e-5f);

    const float4 wv = ((const float4*)w)[tid];
    const float4 bv = ((const float4*)b)[tid];
    float o0 = dx  * inv * wv.x + bv.x;
    float o1 = dy  * inv * wv.y + bv.y;
    float o2 = dz  * inv * wv.z + bv.z;
    float o3 = dww * inv * wv.w + bv.w;
    if (SPLIT) {
        bf16 h0,l0,h1,l1,h2,l2,h3,l3;
        split2(o0,h0,l0); split2(o1,h1,l1); split2(o2,h2,l2); split2(o3,h3,l3);
        __nv_bfloat162* ph = (__nv_bfloat162*)(outh + (size_t)m * D_ + tid * 4);
        __nv_bfloat162* pl = (__nv_bfloat162*)(outl + (size_t)m * D_ + tid * 4);
        ph[0] = __nv_bfloat162(h0, h1); ph[1] = __nv_bfloat162(h2, h3);
        pl[0] = __nv_bfloat162(l0, l1); pl[1] = __nv_bfloat162(l2, l3);
    } else {
        ((float4*)(outf + (size_t)m * D_))[tid] = make_float4(o0, o1, o2, o3);
    }
}

// ------------------------------- weight split ------------------------------
__global__ __launch_bounds__(256)
void cvt_split_kernel(const float* __restrict__ in, bf16* __restrict__ hi,
                      bf16* __restrict__ lo, int n_valid, int n_total)
{
    const int idx = blockIdx.x * 256 + threadIdx.x;
    if (idx >= n_total) return;
    const float v = (idx < n_valid) ? in[idx] : 0.f;
    bf16 h, l; split2(v, h, l);
    hi[idx] = h; lo[idx] = l;
}

// ------------------------------- im2col (split) ----------------------------
__global__ __launch_bounds__(256)
void im2col_kernel(const float* __restrict__ mel)
{
    const int idx = blockIdx.x * 256 + threadIdx.x;
    if (idx >= BT_ * KEMB_) return;
    const int m = idx / KEMB_;
    const int j = idx - m * KEMB_;
    const int c = j / 7, k = j - c * 7;
    const int bb = m >> 11, tt = m & (T_ - 1);
    const int t2 = tt + k - 3;
    const float v = ((unsigned)t2 < (unsigned)T_)
                  ? mel[((size_t)bb * CM_ + c) * T_ + t2] : 0.f;
    bf16 h, l; split2(v, h, l);
    g_i2c_h[idx] = h; g_i2c_l[idx] = l;
}

// ------------------------------- S_cat (split, ld KPAD_) -------------------
__global__ __launch_bounds__(256)
void scat_kernel()
{
    const int idx = blockIdx.x * 256 + threadIdx.x;
    if (idx >= BT_ * NF_) return;
    const int m = idx / NF_;
    const int f = idx - m * NF_;
    const float* ho = g_head + (size_t)m * TWO_NF_;
    const float mag = fminf(expf(ho[f]), 100.f);
    const float ph  = ho[NF_ + f];
    float sp, cp;
    sincosf(ph, &sp, &cp);
    bf16* sh = g_i2c_h + (size_t)m * KPAD_;
    bf16* sl = g_i2c_l + (size_t)m * KPAD_;
    bf16 h, l;
    split2(mag * cp, h, l);  sh[f] = h;        sl[f] = l;
    split2(mag * sp, h, l);  sh[NF_ + f] = h;  sl[NF_ + f] = l;
    if (f < KPAD_ - TWO_NF_) {
        sh[TWO_NF_ + f] = __float2bfloat16_rn(0.f);
        sl[TWO_NF_ + f] = __float2bfloat16_rn(0.f);
    }
}

// ------------------------------- iSTFT basis (split, ld KPAD_) -------------
__global__ __launch_bounds__(256)
void basis_kernel(const float* __restrict__ window)
{
    const int idx = blockIdx.x * 256 + threadIdx.x;
    if (idx >= NFFT_ * NF_) return;
    const int n = idx / NF_;
    const int f = idx - n * NF_;
    const float scale = (f == 0 || f == NF_ - 1) ? (1.f / 1024.f) : (2.f / 1024.f);
    const float a1  = 6.28318530717958647692f * (float)n;
    const float ang = (a1 * (float)f) * (1.f / 1024.f);
    float s, c;
    sincosf(ang, &s, &c);
    const float wn = window[n] * scale;
    bf16* bh = g_bas_h + (size_t)n * KPAD_;
    bf16* bl = g_bas_l + (size_t)n * KPAD_;
    bf16 h, l;
    split2( c * wn, h, l);  bh[f] = h;        bl[f] = l;
    split2(-s * wn, h, l);  bh[NF_ + f] = h;  bl[NF_ + f] = l;
    if (f < KPAD_ - TWO_NF_) {
        bh[TWO_NF_ + f] = __float2bfloat16_rn(0.f);
        bl[TWO_NF_ + f] = __float2bfloat16_rn(0.f);
    }
}

// ------------------------------- overlap-add -------------------------------
__global__ __launch_bounds__(256)
void ola_kernel(const float* __restrict__ window, float* __restrict__ out)
{
    const int idx = blockIdx.x * 256 + threadIdx.x;
    if (idx >= B_ * L_OUT_) return;
    const int b  = idx / L_OUT_;
    const int lo = idx - b * L_OUT_;
    const int l  = lo + NFFT_ / 2;

    int thi = l >> 8;              if (thi > T_ - 1) thi = T_ - 1;
    int tlo = (l - (NFFT_ - 1) + (HOP_ - 1)) >> 8;  if (tlo < 0) tlo = 0;

    float a = 0.f, e = 0.f;
    for (int t = tlo; t <= thi; t++) {
        const int n = l - (t << 8);
        a += g_frames[((size_t)(b * T_ + t) << 10) + n];
        const float wv = window[n];
        e += wv * wv;
    }
    out[idx] = a / (e + 1e-11f);
}

// ------------------------------- launch ------------------------------------
extern "C" void kernel_launch(void* const* d_in, const int* in_sizes, int n_in,
                              void* d_out, int out_size)
{
    const float* mel     = (const float*)d_in[0];
    const float* embed_w = (const float*)d_in[1];
    const float* embed_b = (const float*)d_in[2];
    const float* norm_w  = (const float*)d_in[3];
    const float* norm_b  = (const float*)d_in[4];
    const float* dw_w    = (const float*)d_in[5];
    const float* dw_b    = (const float*)d_in[6];
    const float* bn_w    = (const float*)d_in[7];
    const float* bn_b    = (const float*)d_in[8];
    const float* pw1_w   = (const float*)d_in[9];
    const float* pw1_b   = (const float*)d_in[10];
    const float* pw2_w   = (const float*)d_in[11];
    const float* pw2_b   = (const float*)d_in[12];
    const float* gamma   = (const float*)d_in[13];
    const float* fnorm_w = (const float*)d_in[14];
    const float* fnorm_b = (const float*)d_in[15];
    const float* head_w  = (const float*)d_in[16];
    const float* head_b  = (const float*)d_in[17];
    const float* window  = (const float*)d_in[18];
    float* out = (float*)d_out;

    float *p_x, *p_y, *p_head, *p_frames;
    bf16 *p_i2c_h, *p_i2c_l, *p_yn_h, *p_yn_l, *p_hh, *p_hl, *p_bh, *p_bl, *p_wh, *p_wl;
    cudaGetSymbolAddress((void**)&p_x,      g_x);
    cudaGetSymbolAddress((void**)&p_y,      g_y);
    cudaGetSymbolAddress((void**)&p_head,   g_head);
    cudaGetSymbolAddress((void**)&p_frames, g_frames);
    cudaGetSymbolAddress((void**)&p_i2c_h,  g_i2c_h);
    cudaGetSymbolAddress((void**)&p_i2c_l,  g_i2c_l);
    cudaGetSymbolAddress((void**)&p_yn_h,   g_yn_h);
    cudaGetSymbolAddress((void**)&p_yn_l,   g_yn_l);
    cudaGetSymbolAddress((void**)&p_hh,     g_hh);
    cudaGetSymbolAddress((void**)&p_hl,     g_hl);
    cudaGetSymbolAddress((void**)&p_bh,     g_bas_h);
    cudaGetSymbolAddress((void**)&p_bl,     g_bas_l);
    cudaGetSymbolAddress((void**)&p_wh,     g_wh);
    cudaGetSymbolAddress((void**)&p_wl,     g_wl);

    cudaFuncSetAttribute(bgemm<EPI_BIAS>, cudaFuncAttributeMaxDynamicSharedMemorySize, SMEM_DYN);
    cudaFuncSetAttribute(bgemm<EPI_GELU>, cudaFuncAttributeMaxDynamicSharedMemorySize, SMEM_DYN);
    cudaFuncSetAttribute(bgemm<EPI_RES >, cudaFuncAttributeMaxDynamicSharedMemorySize, SMEM_DYN);
    cudaFuncSetAttribute(bgemm<EPI_NONE>, cudaFuncAttributeMaxDynamicSharedMemorySize, SMEM_DYN);

    const dim3 blk(256);
    const int MT = BT_ / 128;

    // 0) split weights into bf16 hi/lo (head padded with zero rows)
    cvt_split_kernel<<<(N_WE + 255) / 256, blk>>>(embed_w, p_wh + OFF_WE, p_wl + OFF_WE, N_WE, N_WE);
    cvt_split_kernel<<<(N_P1 + 255) / 256, blk>>>(pw1_w,   p_wh + OFF_P1, p_wl + OFF_P1, N_P1, N_P1);
    cvt_split_kernel<<<(N_P2 + 255) / 256, blk>>>(pw2_w,   p_wh + OFF_P2, p_wl + OFF_P2, N_P2, N_P2);
    cvt_split_kernel<<<(N_HD + 255) / 256, blk>>>(head_w,  p_wh + OFF_HD, p_wl + OFF_HD,
                                                  TWO_NF_ * D_, N_HD);

    // 1) embed conv: im2col(split) + GEMM (N=512, K=1344), LN -> x (fp32)
    im2col_kernel<<<(BT_ * KEMB_ + 255) / 256, blk>>>(mel);
    bgemm<EPI_BIAS><<<dim3(D_ / 128, MT), blk, SMEM_DYN>>>(
        p_i2c_h, p_i2c_l, p_wh + OFF_WE, p_wl + OFF_WE,
        embed_b, nullptr, p_y, nullptr, nullptr, D_, KEMB_, KEMB_, KEMB_, D_);
    ln_kernel<false><<<BT_, 128>>>(p_y, p_x, nullptr, nullptr, norm_w, norm_b);

    // 2) 8 ConvNeXt blocks: fused dwconv+LN+split, pw1(GELU->split), pw2(residual)
    for (int i = 0; i < 8; i++) {
        dwln_kernel<<<BT_, 128>>>(p_x, dw_w + (size_t)i * D_ * 7, dw_b + (size_t)i * D_,
                                  bn_w + (size_t)i * D_, bn_b + (size_t)i * D_,
                                  p_yn_h, p_yn_l);
        bgemm<EPI_GELU><<<dim3(H_ / 128, MT), blk, SMEM_DYN>>>(
            p_yn_h, p_yn_l, p_wh + OFF_P1 + (size_t)i * H_ * D_, p_wl + OFF_P1 + (size_t)i * H_ * D_,
            pw1_b + (size_t)i * H_, nullptr, nullptr, p_hh, p_hl, H_, D_, D_, D_, H_);
        bgemm<EPI_RES><<<dim3(D_ / 128, MT), blk, SMEM_DYN>>>(
            p_hh, p_hl, p_wh + OFF_P2 + (size_t)i * D_ * H_, p_wl + OFF_P2 + (size_t)i * D_ * H_,
            pw2_b + (size_t)i * D_, gamma + (size_t)i * D_, p_x, nullptr, nullptr,
            D_, H_, H_, H_, D_);
    }

    // 3) final LN (split) + head (N=1026, K=512, B rows padded to 1152)
    ln_kernel<true><<<BT_, 128>>>(p_x, nullptr, p_yn_h, p_yn_l, fnorm_w, fnorm_b);
    bgemm<EPI_BIAS><<<dim3(NHEADP_ / 128, MT), blk, SMEM_DYN>>>(
        p_yn_h, p_yn_l, p_wh + OFF_HD, p_wl + OFF_HD,
        head_b, nullptr, p_head, nullptr, nullptr, TWO_NF_, D_, D_, D_, TWO_NF_);

    // 4) iSTFT: S_cat(split, K padded), basis(split), frames GEMM, overlap-add
    scat_kernel<<<(BT_ * NF_ + 255) / 256, blk>>>();
    basis_kernel<<<(NFFT_ * NF_ + 255) / 256, blk>>>(window);
    bgemm<EPI_NONE><<<dim3(NFFT_ / 128, MT), blk, SMEM_DYN>>>(
        p_i2c_h, p_i2c_l, p_bh, p_bl, nullptr, nullptr, p_frames, nullptr, nullptr,
        NFFT_, KPAD_, KPAD_, KPAD_, NFFT_);
    ola_kernel<<<(B_ * L_OUT_ + 255) / 256, blk>>>(window, out);
}